// round 12
// baseline (speedup 1.0000x reference)
#include <cuda_runtime.h>

// FilterLayer: y[b,c,h,w] = sum_{i,j in 5x5} x_pad[b,c,h+i,w+j] * f[b,i*5+j,h,w]
// x [4,3,512,512] f32, f [4,25,512,512] f32, out [4,3,512,512] f32.
//
// f (104.9 MB, zero reuse) streams through smem via cp.async, split into 5
// per-tap-row groups so compute on row i overlaps the loads of rows i+1..4.

#define Hc 512
#define Wc 512
#define Bc 4
#define Cc 3
#define WIN 5
#define NK (WIN * WIN)
#define PAD (WIN / 2)

#define TILE_W 128
#define TILE_H 4
#define TW (TILE_W + 2 * PAD)   // 132
#define TH (TILE_H + 2 * PAD)   // 8

#define F_FLOATS (NK * TILE_H * TILE_W)   // 12800 floats = 51200 B
#define GROUP_F4 (WIN * TILE_H * TILE_W / 4)  // 640 float4 per tap-row group
#define X_FLOATS (Cc * TH * TW)           // 3168 floats = 12672 B
#define SMEM_BYTES ((F_FLOATS + X_FLOATS) * 4)  // 63872 B

__device__ __forceinline__ void cp_async16(void* smem_dst, const void* gmem_src) {
    unsigned saddr = (unsigned)__cvta_generic_to_shared(smem_dst);
    asm volatile("cp.async.cg.shared.global [%0], [%1], 16;\n"
                 :: "r"(saddr), "l"(gmem_src) : "memory");
}

__device__ __forceinline__ void cp_wait_groups(int n) {
    switch (n) {
        case 0: asm volatile("cp.async.wait_group 0;\n" ::: "memory"); break;
        case 1: asm volatile("cp.async.wait_group 1;\n" ::: "memory"); break;
        case 2: asm volatile("cp.async.wait_group 2;\n" ::: "memory"); break;
        case 3: asm volatile("cp.async.wait_group 3;\n" ::: "memory"); break;
        default: asm volatile("cp.async.wait_group 4;\n" ::: "memory"); break;
    }
}

__global__ __launch_bounds__(256, 3)
void filter5x5_kernel(const float* __restrict__ x,
                      const float* __restrict__ f,
                      float* __restrict__ out)
{
    extern __shared__ float smem[];
    float* fs = smem;              // [25][TILE_H][TILE_W]
    float* xs = smem + F_FLOATS;   // [Cc][TH][TW]

    const int tid = threadIdx.x;   // 0..255
    const int b   = blockIdx.z;
    const int h0  = blockIdx.y * TILE_H;
    const int w0  = blockIdx.x * TILE_W;

    // ---- issue f tile as 5 cp.async groups (one per tap row) ----
    #pragma unroll
    for (int i = 0; i < WIN; i++) {
        #pragma unroll 1
        for (int idx = tid; idx < GROUP_F4; idx += 256) {
            const int t    = idx >> 7;          // tap within row (128 float4/tap)
            const int rem  = idx & 127;
            const int row  = rem >> 5;
            const int col4 = rem & 31;
            const int tap  = i * WIN + t;
            const float* src = f + (((size_t)(b * NK + tap) * Hc + (h0 + row)) * Wc
                                    + w0 + col4 * 4);
            cp_async16(fs + (tap * TILE_H + row) * TILE_W + col4 * 4, src);
        }
        asm volatile("cp.async.commit_group;\n" ::: "memory");
    }

    // ---- x halo (scalar, mostly L2-resident; overlaps the async f stream) ----
    #pragma unroll
    for (int it = 0; it < (X_FLOATS + 255) / 256; it++) {
        const int idx = tid + it * 256;
        if (idx < X_FLOATS) {
            const int c   = idx / (TH * TW);
            const int rem = idx - c * (TH * TW);
            const int r   = rem / TW;
            const int cc  = rem - r * TW;
            const int gh  = h0 + r - PAD;
            const int gw  = w0 + cc - PAD;
            float v = 0.0f;
            if (gh >= 0 && gh < Hc && gw >= 0 && gw < Wc)
                v = x[((b * Cc + c) * Hc + gh) * Wc + gw];
            xs[idx] = v;
        }
    }
    __syncthreads();   // x tile visible to all threads

    // ---- compute: thread -> 2 adjacent pixels, 3 channels ----
    const int tx = tid & 63;   // 0..63 -> w pair
    const int ty = tid >> 6;   // 0..3  -> row
    const int h  = h0 + ty;
    const int w  = w0 + tx * 2;

    float acc[Cc][2];
    #pragma unroll
    for (int c = 0; c < Cc; c++) { acc[c][0] = 0.0f; acc[c][1] = 0.0f; }

    #pragma unroll
    for (int i = 0; i < WIN; i++) {
        // tap-row i's group must have landed; rows i+1..4 stay in flight
        cp_wait_groups(WIN - 1 - i);
        __syncthreads();

        // x window per channel: cols [2tx .. 2tx+5] of halo row ty+i
        float xr[Cc][6];
        #pragma unroll
        for (int c = 0; c < Cc; c++) {
            const float2* row2 = reinterpret_cast<const float2*>(
                &xs[(c * TH + ty + i) * TW]);
            const float2 q0 = row2[tx];
            const float2 q1 = row2[tx + 1];
            const float2 q2 = row2[tx + 2];
            xr[c][0] = q0.x; xr[c][1] = q0.y;
            xr[c][2] = q1.x; xr[c][3] = q1.y;
            xr[c][4] = q2.x; xr[c][5] = q2.y;
        }
        #pragma unroll
        for (int j = 0; j < WIN; j++) {
            const float2 fk = reinterpret_cast<const float2*>(
                &fs[((i * WIN + j) * TILE_H + ty) * TILE_W])[tx];
            #pragma unroll
            for (int c = 0; c < Cc; c++) {
                acc[c][0] = fmaf(fk.x, xr[c][j + 0], acc[c][0]);
                acc[c][1] = fmaf(fk.y, xr[c][j + 1], acc[c][1]);
            }
        }
    }

    #pragma unroll
    for (int c = 0; c < Cc; c++) {
        float2 o = make_float2(acc[c][0], acc[c][1]);
        *reinterpret_cast<float2*>(out + ((b * Cc + c) * Hc + h) * Wc + w) = o;
    }
}

extern "C" void kernel_launch(void* const* d_in, const int* in_sizes, int n_in,
                              void* d_out, int out_size)
{
    const float* x = (const float*)d_in[0];
    const float* f = (const float*)d_in[1];
    float* out = (float*)d_out;
    (void)in_sizes; (void)n_in; (void)out_size;

    cudaFuncSetAttribute(filter5x5_kernel,
                         cudaFuncAttributeMaxDynamicSharedMemorySize, SMEM_BYTES);

    dim3 block(256, 1, 1);
    dim3 grid(Wc / TILE_W, Hc / TILE_H, Bc); // (4, 128, 4) = 2048 blocks
    filter5x5_kernel<<<grid, block, SMEM_BYTES>>>(x, f, out);
}

// round 17
// speedup vs baseline: 1.1772x; 1.1772x over previous
#include <cuda_runtime.h>

// FilterLayer: y[b,c,h,w] = sum_{i,j in 5x5} x_pad[b,c,h+i,w+j] * f[b,i*5+j,h,w]
// x [4,3,512,512] f32, f [4,25,512,512] f32, out [4,3,512,512] f32.
//
// f (104.9 MB, zero reuse) streams through smem via cp.async in 5 per-tap-row
// groups. x halo LDGs are issued FIRST so they don't queue behind the f stream
// in the L1tex FIFO — compute starts as soon as f group 0 lands, overlapping
// groups 1..4.

#define Hc 512
#define Wc 512
#define Bc 4
#define Cc 3
#define WIN 5
#define NK (WIN * WIN)
#define PAD (WIN / 2)

#define TILE_W 128
#define TILE_H 4
#define TW (TILE_W + 2 * PAD)   // 132
#define TH (TILE_H + 2 * PAD)   // 8

#define F_FLOATS (NK * TILE_H * TILE_W)       // 12800 floats = 51200 B
#define GROUP_F4 (WIN * TILE_H * TILE_W / 4)  // 640 float4 per tap-row group
#define X_FLOATS (Cc * TH * TW)               // 3168 floats = 12672 B
#define SMEM_BYTES ((F_FLOATS + X_FLOATS) * 4)  // 63872 B

__device__ __forceinline__ void cp_async16(void* smem_dst, const void* gmem_src) {
    unsigned saddr = (unsigned)__cvta_generic_to_shared(smem_dst);
    asm volatile("cp.async.cg.shared.global [%0], [%1], 16;\n"
                 :: "r"(saddr), "l"(gmem_src) : "memory");
}

__device__ __forceinline__ void cp_wait_groups(int n) {
    switch (n) {
        case 0: asm volatile("cp.async.wait_group 0;\n" ::: "memory"); break;
        case 1: asm volatile("cp.async.wait_group 1;\n" ::: "memory"); break;
        case 2: asm volatile("cp.async.wait_group 2;\n" ::: "memory"); break;
        case 3: asm volatile("cp.async.wait_group 3;\n" ::: "memory"); break;
        default: asm volatile("cp.async.wait_group 4;\n" ::: "memory"); break;
    }
}

__global__ __launch_bounds__(256, 3)
void filter5x5_kernel(const float* __restrict__ x,
                      const float* __restrict__ f,
                      float* __restrict__ out)
{
    extern __shared__ float smem[];
    float* fs = smem;              // [25][TILE_H][TILE_W]
    float* xs = smem + F_FLOATS;   // [Cc][TH][TW]

    const int tid = threadIdx.x;   // 0..255
    const int b   = blockIdx.z;
    const int h0  = blockIdx.y * TILE_H;
    const int w0  = blockIdx.x * TILE_W;

    // ---- x halo FIRST: its LDGs enter the L1tex queue ahead of the f stream ----
    // Load into registers (13 per thread max), store to smem after issue so the
    // loads batch (MLP) instead of load->store pairs.
    float xv[(X_FLOATS + 255) / 256];   // 13 regs
    #pragma unroll
    for (int it = 0; it < (X_FLOATS + 255) / 256; it++) {
        const int idx = tid + it * 256;
        float v = 0.0f;
        if (idx < X_FLOATS) {
            const int c   = idx / (TH * TW);
            const int rem = idx - c * (TH * TW);
            const int r   = rem / TW;
            const int cc  = rem - r * TW;
            const int gh  = h0 + r - PAD;
            const int gw  = w0 + cc - PAD;
            if (gh >= 0 && gh < Hc && gw >= 0 && gw < Wc)
                v = x[((b * Cc + c) * Hc + gh) * Wc + gw];
        }
        xv[it] = v;
    }

    // ---- f tile: 5 cp.async groups (one per tap row), issued behind x ----
    #pragma unroll
    for (int i = 0; i < WIN; i++) {
        #pragma unroll 1
        for (int idx = tid; idx < GROUP_F4; idx += 256) {
            const int t    = idx >> 7;          // tap within row (128 float4/tap)
            const int rem  = idx & 127;
            const int row  = rem >> 5;
            const int col4 = rem & 31;
            const int tap  = i * WIN + t;
            const float* src = f + (((size_t)(b * NK + tap) * Hc + (h0 + row)) * Wc
                                    + w0 + col4 * 4);
            cp_async16(fs + (tap * TILE_H + row) * TILE_W + col4 * 4, src);
        }
        asm volatile("cp.async.commit_group;\n" ::: "memory");
    }

    // ---- park x registers in smem (x LDGs complete well before f stream) ----
    #pragma unroll
    for (int it = 0; it < (X_FLOATS + 255) / 256; it++) {
        const int idx = tid + it * 256;
        if (idx < X_FLOATS) xs[idx] = xv[it];
    }

    // ---- compute: thread -> 2 adjacent pixels, 3 channels ----
    const int tx = tid & 63;   // 0..63 -> w pair
    const int ty = tid >> 6;   // 0..3  -> row
    const int h  = h0 + ty;
    const int w  = w0 + tx * 2;

    float acc[Cc][2];
    #pragma unroll
    for (int c = 0; c < Cc; c++) { acc[c][0] = 0.0f; acc[c][1] = 0.0f; }

    #pragma unroll
    for (int i = 0; i < WIN; i++) {
        // tap-row i's group must have landed; rows i+1..4 stay in flight
        cp_wait_groups(WIN - 1 - i);
        __syncthreads();   // also covers x-store visibility on i==0

        // x window per channel: cols [2tx .. 2tx+5] of halo row ty+i
        float xr[Cc][6];
        #pragma unroll
        for (int c = 0; c < Cc; c++) {
            const float2* row2 = reinterpret_cast<const float2*>(
                &xs[(c * TH + ty + i) * TW]);
            const float2 q0 = row2[tx];
            const float2 q1 = row2[tx + 1];
            const float2 q2 = row2[tx + 2];
            xr[c][0] = q0.x; xr[c][1] = q0.y;
            xr[c][2] = q1.x; xr[c][3] = q1.y;
            xr[c][4] = q2.x; xr[c][5] = q2.y;
        }
        #pragma unroll
        for (int j = 0; j < WIN; j++) {
            const float2 fk = reinterpret_cast<const float2*>(
                &fs[((i * WIN + j) * TILE_H + ty) * TILE_W])[tx];
            #pragma unroll
            for (int c = 0; c < Cc; c++) {
                acc[c][0] = fmaf(fk.x, xr[c][j + 0], acc[c][0]);
                acc[c][1] = fmaf(fk.y, xr[c][j + 1], acc[c][1]);
            }
        }
    }

    #pragma unroll
    for (int c = 0; c < Cc; c++) {
        float2 o = make_float2(acc[c][0], acc[c][1]);
        *reinterpret_cast<float2*>(out + ((b * Cc + c) * Hc + h) * Wc + w) = o;
    }
}

extern "C" void kernel_launch(void* const* d_in, const int* in_sizes, int n_in,
                              void* d_out, int out_size)
{
    const float* x = (const float*)d_in[0];
    const float* f = (const float*)d_in[1];
    float* out = (float*)d_out;
    (void)in_sizes; (void)n_in; (void)out_size;

    cudaFuncSetAttribute(filter5x5_kernel,
                         cudaFuncAttributeMaxDynamicSharedMemorySize, SMEM_BYTES);

    dim3 block(256, 1, 1);
    dim3 grid(Wc / TILE_W, Hc / TILE_H, Bc); // (4, 128, 4) = 2048 blocks
    filter5x5_kernel<<<grid, block, SMEM_BYTES>>>(x, f, out);
}